// round 9
// baseline (speedup 1.0000x reference)
#include <cuda_runtime.h>
#include <cuda_bf16.h>
#include <math.h>
#include <stdint.h>

// Problem constants
#define BQ 32
#define WQ 64
#define MQ 16
#define LQ 8192
#define NBQ 32
#define KSPL 16

// ---------------- scratch (device globals: allocation-free rule) ----------
__device__ __align__(16) uint32_t g_hpkA[BQ * WQ * LQ];   // packed bf16 hi|lo h (64 MB)
__device__ __align__(16) uint32_t g_hpkB[BQ * WQ * LQ];   // 64 MB
__device__ __align__(16) uint32_t g_Tpk[NBQ * LQ];        // packed basis [n][l] (1 MB)
__device__ __align__(16) uint32_t g_Bhi[NBQ * LQ];        // (T_hi,T_hi) pairs [n][l] (1 MB)
__device__ __align__(16) uint32_t g_Blo[NBQ * LQ];        // (T_lo,T_lo) pairs [n][l] (1 MB)
__device__ float    g_Fpart[BQ * NBQ * KSPL * WQ];        // DFT partials [b][n][p][c]
__device__ uint32_t g_coefpk[BQ * WQ * NBQ];              // packed coef (1 MB)
__device__ uint32_t g_convpk[4 * WQ * WQ];                // packed conv weights

__device__ __forceinline__ float gelu_exact(float v) {
    return 0.5f * v * (1.0f + erff(v * 0.70710678118654752440f));
}

// bf16 hi/lo packing: low 16 bits = hi part, high 16 bits = lo part
__device__ __forceinline__ uint32_t pk(float v) {
    __nv_bfloat16 h = __float2bfloat16(v);
    __nv_bfloat16 l = __float2bfloat16(v - __bfloat162float(h));
    return (uint32_t)__bfloat16_as_ushort(h) | ((uint32_t)__bfloat16_as_ushort(l) << 16);
}

// warp-level bf16 MMA (baseline PTX, sm_80+; tensor pipe)
__device__ __forceinline__ void mma16816(float* d, const uint32_t* a,
                                         uint32_t b0, uint32_t b1) {
    asm volatile(
        "mma.sync.aligned.m16n8k16.row.col.f32.bf16.bf16.f32 "
        "{%0,%1,%2,%3}, {%4,%5,%6,%7}, {%8,%9}, {%0,%1,%2,%3};"
        : "+f"(d[0]), "+f"(d[1]), "+f"(d[2]), "+f"(d[3])
        : "r"(a[0]), "r"(a[1]), "r"(a[2]), "r"(a[3]), "r"(b0), "r"(b1));
}

// fused kernel smem layout (bytes)
#define AS_B 404
#define OFF_A   0
#define OFF_BHI 51712
#define OFF_BLO 77568
#define FUSED_SMEM 103424

// fwd kernel smem: staged tiles (stride 132 words -> conflict-free frags),
// overlaid by the Dw reduction buffer after the mainloop.
#define AW 132
#define FW_BH (64 * AW)                // word offset of B_hi tile
#define FW_BL (96 * AW)                // word offset of B_lo tile
#define DW_STRIDE 68
#define FWD_SMEM (8 * 32 * DW_STRIDE * 4)   // 69632 > 128*AW*4=67584

// ---------------------------------------------------------------------------
// Basis tables: packed pairs for fused A-tiles, (hi,hi)/(lo,lo) for fwd B.
// ---------------------------------------------------------------------------
__global__ void build_table_kernel() {
    int idx = blockIdx.x * blockDim.x + threadIdx.x;  // 131072
    int k = idx >> 13;
    int l = idx & (LQ - 1);
    int m = (k * l) & (LQ - 1);
    float ang = (float)m * (6.283185307179586476925f / (float)LQ);
    float s, c;
    sincosf(ang, &s, &c);
    uint32_t cp = pk(c), sp = pk(s);
    g_Tpk[(2 * k) * LQ + l]     = cp;
    g_Tpk[(2 * k + 1) * LQ + l] = sp;
    uint32_t ch = cp & 0xFFFFu, cl = cp >> 16;
    uint32_t sh = sp & 0xFFFFu, sl = sp >> 16;
    g_Bhi[(2 * k) * LQ + l]     = ch | (ch << 16);
    g_Blo[(2 * k) * LQ + l]     = cl | (cl << 16);
    g_Bhi[(2 * k + 1) * LQ + l] = sh | (sh << 16);
    g_Blo[(2 * k + 1) * LQ + l] = sl | (sl << 16);
}

__global__ void convprep_kernel(const float* __restrict__ cw) {
    int idx = blockIdx.x * 256 + threadIdx.x;   // 16384
    g_convpk[idx] = pk(cw[idx]);
}

// ---------------------------------------------------------------------------
// Lifting -> packed h
// ---------------------------------------------------------------------------
__global__ void lift_kernel(const float* __restrict__ x,
                            const float* __restrict__ Pw,
                            const float* __restrict__ Pb,
                            uint32_t* __restrict__ hpk) {
    int idx = blockIdx.x * 256 + threadIdx.x;
    int l = idx & (LQ - 1);
    int w = (idx >> 13) & 63;
    int b = idx >> 19;
    float x0 = x[(b * 2 + 0) * LQ + l];
    float x1 = x[(b * 2 + 1) * LQ + l];
    hpk[idx] = pk(Pw[2 * w] * x0 + Pw[2 * w + 1] * x1 + Pb[w]);
}

// ---------------------------------------------------------------------------
// Forward DFT via mma.sync bf16-split, SMEM-STAGED (fixes R8 sector shatter):
//   Fpart[b,ks][c=64, n=32] = sum over 512-l slice of h[c,l] * T[l,n]
// 4 chunks of 128 l-words: coalesced LDG into As[64][132], Bh/Bl[32][132];
// fragment LDS banks = 4r+q (all distinct). 8 warps K-split 2 ksteps/chunk,
// all 4x4 m16n8 tiles (64 fp32 acc). Conflict-free Dw reduce, coalesced store.
// ---------------------------------------------------------------------------
__global__ void __launch_bounds__(256) fwd_mma_kernel(const uint32_t* __restrict__ hpk) {
    extern __shared__ __align__(16) uint32_t sw[];
    uint32_t* As = sw;                 // [c][AW]
    uint32_t* Bh = sw + FW_BH;         // [n][AW]
    uint32_t* Bl = sw + FW_BL;
    float* Dw = (float*)sw;            // overlay after mainloop
    int b = blockIdx.x;
    int ks = blockIdx.y;
    int t = threadIdx.x;
    int w = t >> 5;
    int lane = t & 31;
    int r = lane >> 2;
    int q = lane & 3;

    float d[4][4][4];
#pragma unroll
    for (int mi = 0; mi < 4; mi++)
#pragma unroll
        for (int ni = 0; ni < 4; ni++)
#pragma unroll
            for (int e = 0; e < 4; e++) d[mi][ni][e] = 0.f;

    const uint32_t* hb = hpk + (size_t)b * 64 * LQ;
    const int base0 = ks * 512;

    for (int chk = 0; chk < 4; chk++) {
        int lb = base0 + chk * 128;
        __syncthreads();
#pragma unroll
        for (int j = 0; j < 32; j++) {          // A: 8192 words, coalesced
            int id = t + 256 * j;
            int lw = id & 127, c = id >> 7;
            As[c * AW + lw] = hb[(size_t)c * LQ + lb + lw];
        }
#pragma unroll
        for (int j = 0; j < 16; j++) {          // B: 2 x 4096 words, coalesced
            int id = t + 256 * j;
            int lw = id & 127, n = id >> 7;
            Bh[n * AW + lw] = g_Bhi[(size_t)n * LQ + lb + lw];
            Bl[n * AW + lw] = g_Blo[(size_t)n * LQ + lb + lw];
        }
        __syncthreads();

#pragma unroll
        for (int i = 0; i < 2; i++) {           // warp w: ksteps 2w, 2w+1
            int k8 = (w * 2 + i) * 8;
            uint32_t a[4][4];
#pragma unroll
            for (int mi = 0; mi < 4; mi++) {
                const uint32_t* ap = As + (mi * 16 + r) * AW + k8;
                a[mi][0] = ap[q];
                a[mi][1] = ap[8 * AW + q];
                a[mi][2] = ap[q + 4];
                a[mi][3] = ap[8 * AW + q + 4];
            }
#pragma unroll
            for (int pass = 0; pass < 2; pass++) {
                const uint32_t* Bt = pass ? Bl : Bh;
#pragma unroll
                for (int ni = 0; ni < 4; ni++) {
                    const uint32_t* bp = Bt + (ni * 8 + r) * AW + k8;
                    uint32_t b0 = bp[q];
                    uint32_t b1 = bp[q + 4];
#pragma unroll
                    for (int mi = 0; mi < 4; mi++)
                        mma16816(d[mi][ni], a[mi], b0, b1);
                }
            }
        }
    }

    __syncthreads();                    // tiles dead; Dw overlay live
    float* dw = Dw + w * (32 * DW_STRIDE);
#pragma unroll
    for (int mi = 0; mi < 4; mi++)
#pragma unroll
        for (int ni = 0; ni < 4; ni++) {
            int c = mi * 16 + r;
            int n = ni * 8 + 2 * q;
            dw[n * DW_STRIDE + c]           = d[mi][ni][0];
            dw[(n + 1) * DW_STRIDE + c]     = d[mi][ni][1];
            dw[n * DW_STRIDE + c + 8]       = d[mi][ni][2];
            dw[(n + 1) * DW_STRIDE + c + 8] = d[mi][ni][3];
        }
    __syncthreads();

#pragma unroll
    for (int j = 0; j < 8; j++) {
        int idx = t + 256 * j;          // 2048 = 32 n x 64 c
        int n = idx >> 6;
        int c = idx & 63;
        float s = 0.f;
#pragma unroll
        for (int ww = 0; ww < 8; ww++)
            s += Dw[ww * (32 * DW_STRIDE) + n * DW_STRIDE + c];
        g_Fpart[((size_t)(b * NBQ + n) * KSPL + ks) * 64 + c] = s;
    }
}

// ---------------------------------------------------------------------------
// Mode mixing -> packed coefficients. (unchanged)
// ---------------------------------------------------------------------------
__global__ void __launch_bounds__(256) mode_mix_kernel(const float* __restrict__ kwr,
                                                       const float* __restrict__ kwi, int ib) {
    int k = blockIdx.x;
    int bg = blockIdx.y;
    int t = threadIdx.x;
    int o = t & 63;
    int bb = t >> 6;
    int b = bg * 4 + bb;
    __shared__ float wrS[64 * 65], wiS[64 * 65];
    __shared__ float HrS[4][64], HsS[4][64];

    const float* wrG = kwr + ((size_t)ib * 16 + k) * 4096;
    const float* wiG = kwi + ((size_t)ib * 16 + k) * 4096;
#pragma unroll
    for (int j = 0; j < 16; j++) {
        int idx = t + 256 * j;
        int row = idx >> 6, col = idx & 63;
        wrS[row * 65 + col] = wrG[idx];
        wiS[row * 65 + col] = wiG[idx];
    }

    float hr = 0.f, hs = 0.f;
    const float* fr = g_Fpart + (size_t)(b * NBQ + 2 * k) * KSPL * 64;
    const float* fs = g_Fpart + (size_t)(b * NBQ + 2 * k + 1) * KSPL * 64;
#pragma unroll
    for (int p = 0; p < KSPL; p++) {
        hr += fr[p * 64 + o];
        hs += fs[p * 64 + o];
    }
    HrS[bb][o] = hr;
    HsS[bb][o] = hs;
    __syncthreads();

    float ar = 0.f, ai = 0.f;
#pragma unroll 8
    for (int i = 0; i < 64; i++) {
        float xr = HrS[bb][i];
        float xi = -HsS[bb][i];
        float wrv = wrS[o * 65 + i];
        float wiv = wiS[o * 65 + i];
        ar += wrv * xr - wiv * xi;
        ai += wrv * xi + wiv * xr;
    }
    const float invL = 1.0f / (float)LQ;
    float cC, cS;
    if (k == 0) { cC = ar * invL;        cS = 0.f; }
    else        { cC = 2.f * ar * invL;  cS = -2.f * ai * invL; }
    g_coefpk[(b * 64 + o) * NBQ + 2 * k]     = pk(cC);
    g_coefpk[(b * 64 + o) * NBQ + 2 * k + 1] = pk(cS);
}

// ---------------------------------------------------------------------------
// Fused block via mma.sync bf16-split. (unchanged — validated)
// ---------------------------------------------------------------------------
template <bool LAST>
__global__ void __launch_bounds__(256) fused_mma_kernel(
    const uint32_t* __restrict__ hin, uint32_t* __restrict__ hout,
    const float* __restrict__ cb, int ib,
    const float* __restrict__ Qw, const float* __restrict__ Qb,
    float* __restrict__ outp) {
    extern __shared__ __align__(16) char smem[];
    char* Asm = smem + OFF_A;
    int b = blockIdx.y;
    int t = threadIdx.x;
    int wid = t >> 5;
    int lane = t & 31;
    int l0 = blockIdx.x * 128;

    const uint32_t* hsrc = hin + (size_t)b * 64 * LQ;
#pragma unroll
    for (int j = 0; j < 48; j++) {
        int id = t + 256 * j;            // 12288 = 96 ch x 128 l
        int c = id >> 7;
        int l = id & 127;
        const uint32_t* src = (c < 32) ? (g_Tpk + (size_t)c * LQ)
                                       : (hsrc + (size_t)(c - 32) * LQ);
        uint32_t u = src[l0 + l];
        *(uint32_t*)(Asm + l * AS_B + c * 4) = u;
    }
#pragma unroll
    for (int j = 0; j < 24; j++) {
        int id = t + 256 * j;            // 6144 = 64 o x 96 c
        int o = id / 96;
        int c = id - o * 96;
        uint32_t u = (c < 32) ? g_coefpk[((size_t)b * 64 + o) * NBQ + c]
                              : g_convpk[ib * 4096 + o * 64 + (c - 32)];
        uint32_t wh = u & 0xFFFFu;
        uint32_t wl = u >> 16;
        *(uint32_t*)(smem + OFF_BHI + o * AS_B + c * 4) = wh | (wh << 16);
        *(uint32_t*)(smem + OFF_BLO + o * AS_B + c * 4) = wl | (wl << 16);
    }
    __syncthreads();

    int wm = wid >> 1;
    int wn = wid & 1;
    int r = lane >> 2;
    int q = lane & 3;
    float d[2][4][4];
#pragma unroll
    for (int mi = 0; mi < 2; mi++)
#pragma unroll
        for (int ni = 0; ni < 4; ni++)
#pragma unroll
            for (int e = 0; e < 4; e++) d[mi][ni][e] = 0.f;

#pragma unroll
    for (int ks = 0; ks < 12; ks++) {
        int kb = (ks * 16 + q * 2) * 2;
        uint32_t a[2][4];
#pragma unroll
        for (int mi = 0; mi < 2; mi++) {
            const char* arow = Asm + (wm * 32 + mi * 16 + r) * AS_B + kb;
            a[mi][0] = *(const uint32_t*)(arow);
            a[mi][1] = *(const uint32_t*)(arow + 8 * AS_B);
            a[mi][2] = *(const uint32_t*)(arow + 16);
            a[mi][3] = *(const uint32_t*)(arow + 8 * AS_B + 16);
        }
#pragma unroll
        for (int pass = 0; pass < 2; pass++) {
            const char* Bp = smem + (pass ? OFF_BLO : OFF_BHI);
#pragma unroll
            for (int ni = 0; ni < 4; ni++) {
                const char* brow = Bp + (wn * 32 + ni * 8 + r) * AS_B + kb;
                uint32_t b0 = *(const uint32_t*)(brow);
                uint32_t b1 = *(const uint32_t*)(brow + 16);
                mma16816(d[0][ni], a[0], b0, b1);
                mma16816(d[1][ni], a[1], b0, b1);
            }
        }
    }

    __syncthreads();
    float* D = (float*)Asm;              // D[o][129]
#pragma unroll
    for (int mi = 0; mi < 2; mi++)
#pragma unroll
        for (int ni = 0; ni < 4; ni++) {
            int l = wm * 32 + mi * 16 + r;
            int o = wn * 32 + ni * 8 + q * 2;
            D[o * 129 + l]           = d[mi][ni][0];
            D[(o + 1) * 129 + l]     = d[mi][ni][1];
            D[o * 129 + l + 8]       = d[mi][ni][2];
            D[(o + 1) * 129 + l + 8] = d[mi][ni][3];
        }
    __syncthreads();

    if (!LAST) {
#pragma unroll
        for (int j = 0; j < 32; j++) {
            int idx = t + 256 * j;
            int o = idx >> 7;
            int l = idx & 127;
            float v = D[o * 129 + l] + __ldg(&cb[ib * 64 + o]);
            hout[((size_t)b * 64 + o) * LQ + l0 + l] = pk(gelu_exact(v));
        }
    } else {
        float* partS = (float*)(smem + OFF_BHI);
        int l = t & 127;
        int ob = t >> 7;
        float s = 0.f;
#pragma unroll
        for (int j = 0; j < 32; j++) {
            int o = ob + 2 * j;
            float v = D[o * 129 + l] + __ldg(&cb[ib * 64 + o]);
            s += __ldg(&Qw[o]) * gelu_exact(v);
        }
        partS[ob * 128 + l] = s;
        __syncthreads();
        if (t < 128)
            outp[(size_t)b * LQ + l0 + t] = partS[t] + partS[128 + t] + __ldg(&Qb[0]);
    }
}

// ---------------------------------------------------------------------------
extern "C" void kernel_launch(void* const* d_in, const int* in_sizes, int n_in,
                              void* d_out, int out_size) {
    const float* x   = (const float*)d_in[0];
    const float* Pw  = (const float*)d_in[1];
    const float* Pb  = (const float*)d_in[2];
    const float* kwr = (const float*)d_in[3];
    const float* kwi = (const float*)d_in[4];
    const float* cw  = (const float*)d_in[5];
    const float* cb  = (const float*)d_in[6];
    const float* Qw  = (const float*)d_in[7];
    const float* Qb  = (const float*)d_in[8];
    float* out = (float*)d_out;

    uint32_t *hA = nullptr, *hB = nullptr;
    cudaGetSymbolAddress((void**)&hA, g_hpkA);
    cudaGetSymbolAddress((void**)&hB, g_hpkB);

    cudaFuncSetAttribute(fused_mma_kernel<false>,
                         cudaFuncAttributeMaxDynamicSharedMemorySize, FUSED_SMEM);
    cudaFuncSetAttribute(fused_mma_kernel<true>,
                         cudaFuncAttributeMaxDynamicSharedMemorySize, FUSED_SMEM);
    cudaFuncSetAttribute(fwd_mma_kernel,
                         cudaFuncAttributeMaxDynamicSharedMemorySize, FWD_SMEM);

    build_table_kernel<<<(LQ * MQ) / 256, 256>>>();
    convprep_kernel<<<64, 256>>>(cw);
    lift_kernel<<<(BQ * WQ * LQ) / 256, 256>>>(x, Pw, Pb, hA);

    uint32_t* cur = hA;
    uint32_t* nxt = hB;
    for (int ib = 0; ib < 4; ib++) {
        fwd_mma_kernel<<<dim3(BQ, KSPL), 256, FWD_SMEM>>>(cur);
        mode_mix_kernel<<<dim3(16, 8), 256>>>(kwr, kwi, ib);
        if (ib < 3) {
            fused_mma_kernel<false><<<dim3(LQ / 128, BQ), 256, FUSED_SMEM>>>(
                cur, nxt, cb, ib, Qw, Qb, out);
        } else {
            fused_mma_kernel<true><<<dim3(LQ / 128, BQ), 256, FUSED_SMEM>>>(
                cur, nxt, cb, ib, Qw, Qb, out);
        }
        uint32_t* tmp = cur; cur = nxt; nxt = tmp;
    }
}

// round 11
// speedup vs baseline: 1.1247x; 1.1247x over previous
#include <cuda_runtime.h>
#include <cuda_bf16.h>
#include <math.h>
#include <stdint.h>

// Problem constants
#define BQ 32
#define WQ 64
#define MQ 16
#define LQ 8192
#define LH 4096
#define NBQ 32
#define PSL 64            // Fpart p-slots (l-tiles per batch)

// ---------------- scratch (device globals: allocation-free rule) ----------
__device__ __align__(16) uint32_t g_hpkA[BQ * WQ * LQ];   // packed bf16 hi|lo h (64 MB)
__device__ __align__(16) uint32_t g_hpkB[BQ * WQ * LQ];   // 64 MB
__device__ float    g_T[LQ * NBQ];                        // fp32 basis [l][n] (1 MB)
__device__ __align__(16) uint32_t g_Tpk[NBQ * LQ];        // packed basis [n][l] (1 MB)
__device__ __align__(16) uint32_t g_Bhi[NBQ * LQ];        // (T_hi,T_hi) pairs [n][l]
__device__ __align__(16) uint32_t g_Blo[NBQ * LQ];        // (T_lo,T_lo) pairs [n][l]
__device__ float    g_Fpart[BQ * NBQ * PSL * WQ];         // DFT partials [b][n][p][c] (16MB)
__device__ uint32_t g_coefpk[BQ * WQ * NBQ];              // packed coef (1 MB)
__device__ uint32_t g_convpk[4 * WQ * WQ];                // packed conv weights

__device__ __forceinline__ float gelu_exact(float v) {
    return 0.5f * v * (1.0f + erff(v * 0.70710678118654752440f));
}

// bf16 hi/lo packing: low 16 bits = hi part, high 16 bits = lo part
__device__ __forceinline__ uint32_t pk(float v) {
    __nv_bfloat16 h = __float2bfloat16(v);
    __nv_bfloat16 l = __float2bfloat16(v - __bfloat162float(h));
    return (uint32_t)__bfloat16_as_ushort(h) | ((uint32_t)__bfloat16_as_ushort(l) << 16);
}
__device__ __forceinline__ float upk(uint32_t u) {
    return __bfloat162float(__ushort_as_bfloat16((unsigned short)(u & 0xFFFFu)))
         + __bfloat162float(__ushort_as_bfloat16((unsigned short)(u >> 16)));
}

// warp-level bf16 MMA (baseline PTX, sm_80+; tensor pipe)
__device__ __forceinline__ void mma16816(float* d, const uint32_t* a,
                                         uint32_t b0, uint32_t b1) {
    asm volatile(
        "mma.sync.aligned.m16n8k16.row.col.f32.bf16.bf16.f32 "
        "{%0,%1,%2,%3}, {%4,%5,%6,%7}, {%8,%9}, {%0,%1,%2,%3};"
        : "+f"(d[0]), "+f"(d[1]), "+f"(d[2]), "+f"(d[3])
        : "r"(a[0]), "r"(a[1]), "r"(a[2]), "r"(a[3]), "r"(b0), "r"(b1));
}

// fused kernel smem layout (bytes)
#define AS_B 404
#define OFF_A   0                     // A tiles; post-mainloop: D fp32 [64][129]
#define OFF_BHI 51712                 // B_hi; post-mainloop: G u32 [64][132] (33792)
#define OFF_BLO 77568                 // B_lo
#define OFF_G   51712
#define OFF_P   85504                 // P fp32 [2][64][33] = 16896 -> ends 102400
#define FUSED_SMEM 103424

// ---------------------------------------------------------------------------
// Basis tables.
// ---------------------------------------------------------------------------
__global__ void build_table_kernel() {
    int idx = blockIdx.x * blockDim.x + threadIdx.x;  // 131072
    int k = idx >> 13;
    int l = idx & (LQ - 1);
    int m = (k * l) & (LQ - 1);
    float ang = (float)m * (6.283185307179586476925f / (float)LQ);
    float s, c;
    sincosf(ang, &s, &c);
    g_T[l * NBQ + 2 * k]     = c;
    g_T[l * NBQ + 2 * k + 1] = s;
    uint32_t cp = pk(c), sp = pk(s);
    g_Tpk[(2 * k) * LQ + l]     = cp;
    g_Tpk[(2 * k + 1) * LQ + l] = sp;
    uint32_t ch = cp & 0xFFFFu, cl = cp >> 16;
    uint32_t sh = sp & 0xFFFFu, sl = sp >> 16;
    g_Bhi[(2 * k) * LQ + l]     = ch | (ch << 16);
    g_Blo[(2 * k) * LQ + l]     = cl | (cl << 16);
    g_Bhi[(2 * k + 1) * LQ + l] = sh | (sh << 16);
    g_Blo[(2 * k + 1) * LQ + l] = sl | (sl << 16);
}

__global__ void convprep_kernel(const float* __restrict__ cw) {
    int idx = blockIdx.x * 256 + threadIdx.x;   // 16384
    g_convpk[idx] = pk(cw[idx]);
}

// ---------------------------------------------------------------------------
// Lifting -> packed h
// ---------------------------------------------------------------------------
__global__ void lift_kernel(const float* __restrict__ x,
                            const float* __restrict__ Pw,
                            const float* __restrict__ Pb,
                            uint32_t* __restrict__ hpk) {
    int idx = blockIdx.x * 256 + threadIdx.x;
    int l = idx & (LQ - 1);
    int w = (idx >> 13) & 63;
    int b = idx >> 19;
    float x0 = x[(b * 2 + 0) * LQ + l];
    float x1 = x[(b * 2 + 1) * LQ + l];
    hpk[idx] = pk(Pw[2 * w] * x0 + Pw[2 * w + 1] * x1 + Pb[w]);
}

// ---------------------------------------------------------------------------
// Scalar forward DFT with half-period folding — LAYER 0 ONLY (validated R5/R7).
// Grid (BQ, 16); writes Fpart p = ks (0..15).
// ---------------------------------------------------------------------------
__global__ void __launch_bounds__(128) fwd_dft_kernel(const uint32_t* __restrict__ hpk) {
    __shared__ float Es[64 * 65];
    __shared__ float Os[64 * 65];
    __shared__ __align__(16) float Tt[64 * 32];
    int b = blockIdx.x;
    int ks = blockIdx.y;
    int t = threadIdx.x;
    int cc = t & 31;
    int nq = (t >> 5) << 3;
    float acc0[8] = {0.f,0.f,0.f,0.f,0.f,0.f,0.f,0.f};
    float acc1[8] = {0.f,0.f,0.f,0.f,0.f,0.f,0.f,0.f};
    const int lbase = ks * (LH / 16);  // 256

    for (int chk = 0; chk < 4; chk++) {
        int l0 = lbase + chk * 64;
        __syncthreads();
#pragma unroll
        for (int j = 0; j < 32; j++) {
            int idx = t + 128 * j;
            int c = idx >> 6, l = idx & 63;
            const uint32_t* hp = hpk + (size_t)(b * 64 + c) * LQ + l0 + l;
            float v1 = upk(hp[0]);
            float v2 = upk(hp[LH]);
            Es[c * 65 + l] = v1 + v2;
            Os[c * 65 + l] = v1 - v2;
        }
#pragma unroll
        for (int j = 0; j < 4; j++) {
            int idx = t + 128 * j;
            ((float4*)Tt)[idx] = ((const float4*)g_T)[l0 * 8 + idx];
        }
        __syncthreads();
#pragma unroll 4
        for (int l = 0; l < 64; l++) {
            float e0 = Es[cc * 65 + l];
            float e1 = Es[(cc + 32) * 65 + l];
            float o0 = Os[cc * 65 + l];
            float o1 = Os[(cc + 32) * 65 + l];
            float4 bv0 = *(float4*)(Tt + l * 32 + nq);
            float4 bv1 = *(float4*)(Tt + l * 32 + nq + 4);
            acc0[0] += e0 * bv0.x; acc0[1] += e0 * bv0.y;
            acc0[2] += o0 * bv0.z; acc0[3] += o0 * bv0.w;
            acc0[4] += e0 * bv1.x; acc0[5] += e0 * bv1.y;
            acc0[6] += o0 * bv1.z; acc0[7] += o0 * bv1.w;
            acc1[0] += e1 * bv0.x; acc1[1] += e1 * bv0.y;
            acc1[2] += o1 * bv0.z; acc1[3] += o1 * bv0.w;
            acc1[4] += e1 * bv1.x; acc1[5] += e1 * bv1.y;
            acc1[6] += o1 * bv1.z; acc1[7] += o1 * bv1.w;
        }
    }
#pragma unroll
    for (int j = 0; j < 8; j++) {
        int n = nq + j;
        size_t base = ((size_t)(b * NBQ + n) * PSL + ks) * 64;
        g_Fpart[base + cc]      = acc0[j];
        g_Fpart[base + cc + 32] = acc1[j];
    }
}

// ---------------------------------------------------------------------------
// Mode mixing -> packed coefficients; pcount = #valid Fpart p-slots.
// ---------------------------------------------------------------------------
__global__ void __launch_bounds__(256) mode_mix_kernel(const float* __restrict__ kwr,
                                                       const float* __restrict__ kwi,
                                                       int ib, int pcount) {
    int k = blockIdx.x;
    int bg = blockIdx.y;
    int t = threadIdx.x;
    int o = t & 63;
    int bb = t >> 6;
    int b = bg * 4 + bb;
    __shared__ float wrS[64 * 65], wiS[64 * 65];
    __shared__ float HrS[4][64], HsS[4][64];

    const float* wrG = kwr + ((size_t)ib * 16 + k) * 4096;
    const float* wiG = kwi + ((size_t)ib * 16 + k) * 4096;
#pragma unroll
    for (int j = 0; j < 16; j++) {
        int idx = t + 256 * j;
        int row = idx >> 6, col = idx & 63;
        wrS[row * 65 + col] = wrG[idx];
        wiS[row * 65 + col] = wiG[idx];
    }

    float hr = 0.f, hs = 0.f;
    const float* fr = g_Fpart + (size_t)(b * NBQ + 2 * k) * PSL * 64;
    const float* fs = g_Fpart + (size_t)(b * NBQ + 2 * k + 1) * PSL * 64;
#pragma unroll 16
    for (int p = 0; p < pcount; p++) {
        hr += fr[p * 64 + o];
        hs += fs[p * 64 + o];
    }
    HrS[bb][o] = hr;
    HsS[bb][o] = hs;
    __syncthreads();

    float ar = 0.f, ai = 0.f;
#pragma unroll 8
    for (int i = 0; i < 64; i++) {
        float xr = HrS[bb][i];
        float xi = -HsS[bb][i];
        float wrv = wrS[o * 65 + i];
        float wiv = wiS[o * 65 + i];
        ar += wrv * xr - wiv * xi;
        ai += wrv * xi + wiv * xr;
    }
    const float invL = 1.0f / (float)LQ;
    float cC, cS;
    if (k == 0) { cC = ar * invL;        cS = 0.f; }
    else        { cC = 2.f * ar * invL;  cS = -2.f * ai * invL; }
    g_coefpk[(b * 64 + o) * NBQ + 2 * k]     = pk(cC);
    g_coefpk[(b * 64 + o) * NBQ + 2 * k + 1] = pk(cS);
}

// ---------------------------------------------------------------------------
// Fused block via mma.sync bf16-split (validated), PLUS (when !LAST) the
// forward DFT of the produced h tile as a side-GEMM:
//   Fpart[b][n][p=tile][o] = sum_l G[o,l] * T[l0+l, n]
// using the same bf16 hi/lo 2-pass scheme with g_Bhi/g_Blo.
// ---------------------------------------------------------------------------
template <bool LAST>
__global__ void __launch_bounds__(256, 2) fused_mma_kernel(
    const uint32_t* __restrict__ hin, uint32_t* __restrict__ hout,
    const float* __restrict__ cb, int ib,
    const float* __restrict__ Qw, const float* __restrict__ Qb,
    float* __restrict__ outp) {
    extern __shared__ __align__(16) char smem[];
    char* Asm = smem + OFF_A;
    int b = blockIdx.y;
    int t = threadIdx.x;
    int wid = t >> 5;
    int lane = t & 31;
    int l0 = blockIdx.x * 128;

    const uint32_t* hsrc = hin + (size_t)b * 64 * LQ;
#pragma unroll
    for (int j = 0; j < 48; j++) {
        int id = t + 256 * j;            // 12288 = 96 ch x 128 l
        int c = id >> 7;
        int l = id & 127;
        const uint32_t* src = (c < 32) ? (g_Tpk + (size_t)c * LQ)
                                       : (hsrc + (size_t)(c - 32) * LQ);
        uint32_t u = src[l0 + l];
        *(uint32_t*)(Asm + l * AS_B + c * 4) = u;
    }
#pragma unroll
    for (int j = 0; j < 24; j++) {
        int id = t + 256 * j;            // 6144 = 64 o x 96 c
        int o = id / 96;
        int c = id - o * 96;
        uint32_t u = (c < 32) ? g_coefpk[((size_t)b * 64 + o) * NBQ + c]
                              : g_convpk[ib * 4096 + o * 64 + (c - 32)];
        uint32_t wh = u & 0xFFFFu;
        uint32_t wl = u >> 16;
        *(uint32_t*)(smem + OFF_BHI + o * AS_B + c * 4) = wh | (wh << 16);
        *(uint32_t*)(smem + OFF_BLO + o * AS_B + c * 4) = wl | (wl << 16);
    }
    __syncthreads();

    int wm = wid >> 1;
    int wn = wid & 1;
    int r = lane >> 2;
    int q = lane & 3;
    float d[2][4][4];
#pragma unroll
    for (int mi = 0; mi < 2; mi++)
#pragma unroll
        for (int ni = 0; ni < 4; ni++)
#pragma unroll
            for (int e = 0; e < 4; e++) d[mi][ni][e] = 0.f;

#pragma unroll
    for (int ks = 0; ks < 12; ks++) {
        int kb = (ks * 16 + q * 2) * 2;
        uint32_t a[2][4];
#pragma unroll
        for (int mi = 0; mi < 2; mi++) {
            const char* arow = Asm + (wm * 32 + mi * 16 + r) * AS_B + kb;
            a[mi][0] = *(const uint32_t*)(arow);
            a[mi][1] = *(const uint32_t*)(arow + 8 * AS_B);
            a[mi][2] = *(const uint32_t*)(arow + 16);
            a[mi][3] = *(const uint32_t*)(arow + 8 * AS_B + 16);
        }
#pragma unroll
        for (int pass = 0; pass < 2; pass++) {
            const char* Bp = smem + (pass ? OFF_BLO : OFF_BHI);
#pragma unroll
            for (int ni = 0; ni < 4; ni++) {
                const char* brow = Bp + (wn * 32 + ni * 8 + r) * AS_B + kb;
                uint32_t b0 = *(const uint32_t*)(brow);
                uint32_t b1 = *(const uint32_t*)(brow + 16);
                mma16816(d[0][ni], a[0], b0, b1);
                mma16816(d[1][ni], a[1], b0, b1);
            }
        }
    }

    __syncthreads();
    float* D = (float*)Asm;              // D[o][129]
#pragma unroll
    for (int mi = 0; mi < 2; mi++)
#pragma unroll
        for (int ni = 0; ni < 4; ni++) {
            int l = wm * 32 + mi * 16 + r;
            int o = wn * 32 + ni * 8 + q * 2;
            D[o * 129 + l]           = d[mi][ni][0];
            D[(o + 1) * 129 + l]     = d[mi][ni][1];
            D[o * 129 + l + 8]       = d[mi][ni][2];
            D[(o + 1) * 129 + l + 8] = d[mi][ni][3];
        }
    __syncthreads();

    if (!LAST) {
        uint32_t* G = (uint32_t*)(smem + OFF_G);   // [64 o][132 l-words]
#pragma unroll
        for (int j = 0; j < 32; j++) {
            int idx = t + 256 * j;
            int o = idx >> 7;
            int l = idx & 127;
            float v = D[o * 129 + l] + __ldg(&cb[ib * 64 + o]);
            uint32_t g = pk(gelu_exact(v));
            hout[((size_t)b * 64 + o) * LQ + l0 + l] = g;
            G[o * 132 + l] = g;
        }
        __syncthreads();

        // ---- DFT side-GEMM: F[o=64, n=32] = G x T, 2-pass hi/lo ----------
        int wq = wid >> 2;               // k-half 0/1
        int wnn = wid & 3;               // n-tile 0..3
        float f[4][4];
#pragma unroll
        for (int mi = 0; mi < 4; mi++)
#pragma unroll
            for (int e = 0; e < 4; e++) f[mi][e] = 0.f;

#pragma unroll
        for (int kk = 0; kk < 8; kk++) {
            int kw = (wq * 8 + kk) * 8;  // word base within 128-l tile
            uint32_t a[4][4];
#pragma unroll
            for (int mi = 0; mi < 4; mi++) {
                const uint32_t* ap = G + (mi * 16 + r) * 132 + kw;
                a[mi][0] = ap[q];
                a[mi][1] = ap[8 * 132 + q];
                a[mi][2] = ap[q + 4];
                a[mi][3] = ap[8 * 132 + q + 4];
            }
#pragma unroll
            for (int pass = 0; pass < 2; pass++) {
                const uint32_t* Bt = pass ? g_Blo : g_Bhi;
                const uint32_t* bp = Bt + (size_t)(wnn * 8 + r) * LQ + l0 + kw;
                uint32_t b0 = bp[q];
                uint32_t b1 = bp[q + 4];
#pragma unroll
                for (int mi = 0; mi < 4; mi++)
                    mma16816(f[mi], a[mi], b0, b1);
            }
        }

        float* P = (float*)(smem + OFF_P);    // [2][64 o][33 n]
#pragma unroll
        for (int mi = 0; mi < 4; mi++) {
            int o = mi * 16 + r;
            int n = wnn * 8 + 2 * q;
            P[(wq * 64 + o) * 33 + n]           = f[mi][0];
            P[(wq * 64 + o) * 33 + n + 1]       = f[mi][1];
            P[(wq * 64 + o + 8) * 33 + n]       = f[mi][2];
            P[(wq * 64 + o + 8) * 33 + n + 1]   = f[mi][3];
        }
        __syncthreads();

#pragma unroll
        for (int j = 0; j < 8; j++) {
            int idx = t + 256 * j;        // 2048 = 32 n x 64 o
            int n = idx >> 6;
            int o = idx & 63;
            float s = P[o * 33 + n] + P[(64 + o) * 33 + n];
            g_Fpart[(((size_t)b * NBQ + n) * PSL + blockIdx.x) * 64 + o] = s;
        }
    } else {
        float* partS = (float*)(smem + OFF_BHI);
        int l = t & 127;
        int ob = t >> 7;
        float s = 0.f;
#pragma unroll
        for (int j = 0; j < 32; j++) {
            int o = ob + 2 * j;
            float v = D[o * 129 + l] + __ldg(&cb[ib * 64 + o]);
            s += __ldg(&Qw[o]) * gelu_exact(v);
        }
        partS[ob * 128 + l] = s;
        __syncthreads();
        if (t < 128)
            outp[(size_t)b * LQ + l0 + t] = partS[t] + partS[128 + t] + __ldg(&Qb[0]);
    }
}

// ---------------------------------------------------------------------------
extern "C" void kernel_launch(void* const* d_in, const int* in_sizes, int n_in,
                              void* d_out, int out_size) {
    const float* x   = (const float*)d_in[0];
    const float* Pw  = (const float*)d_in[1];
    const float* Pb  = (const float*)d_in[2];
    const float* kwr = (const float*)d_in[3];
    const float* kwi = (const float*)d_in[4];
    const float* cw  = (const float*)d_in[5];
    const float* cb  = (const float*)d_in[6];
    const float* Qw  = (const float*)d_in[7];
    const float* Qb  = (const float*)d_in[8];
    float* out = (float*)d_out;

    uint32_t *hA = nullptr, *hB = nullptr;
    cudaGetSymbolAddress((void**)&hA, g_hpkA);
    cudaGetSymbolAddress((void**)&hB, g_hpkB);

    cudaFuncSetAttribute(fused_mma_kernel<false>,
                         cudaFuncAttributeMaxDynamicSharedMemorySize, FUSED_SMEM);
    cudaFuncSetAttribute(fused_mma_kernel<true>,
                         cudaFuncAttributeMaxDynamicSharedMemorySize, FUSED_SMEM);

    build_table_kernel<<<(LQ * MQ) / 256, 256>>>();
    convprep_kernel<<<64, 256>>>(cw);
    lift_kernel<<<(BQ * WQ * LQ) / 256, 256>>>(x, Pw, Pb, hA);

    // Layer-0 forward DFT (only standalone fwd pass; p-slots 0..15)
    fwd_dft_kernel<<<dim3(BQ, 16), 128>>>(hA);

    uint32_t* cur = hA;
    uint32_t* nxt = hB;
    for (int ib = 0; ib < 4; ib++) {
        int pcount = (ib == 0) ? 16 : PSL;
        mode_mix_kernel<<<dim3(16, 8), 256>>>(kwr, kwi, ib, pcount);
        if (ib < 3) {
            fused_mma_kernel<false><<<dim3(LQ / 128, BQ), 256, FUSED_SMEM>>>(
                cur, nxt, cb, ib, Qw, Qb, out);
        } else {
            fused_mma_kernel<true><<<dim3(LQ / 128, BQ), 256, FUSED_SMEM>>>(
                cur, nxt, cb, ib, Qw, Qb, out);
        }
        uint32_t* tmp = cur; cur = nxt; nxt = tmp;
    }
}

// round 12
// speedup vs baseline: 1.2604x; 1.1206x over previous
#include <cuda_runtime.h>
#include <cuda_bf16.h>
#include <math.h>
#include <stdint.h>

// Problem constants
#define BQ 32
#define WQ 64
#define MQ 16
#define LQ 8192
#define LH 4096
#define NBQ 32
#define KSPL 16

// ---------------- scratch (device globals: allocation-free rule) ----------
__device__ __align__(16) uint32_t g_hpkA[BQ * WQ * LQ];   // packed bf16 hi|lo h (64 MB)
__device__ __align__(16) uint32_t g_hpkB[BQ * WQ * LQ];   // 64 MB
__device__ float    g_T[LQ * NBQ];                        // fp32 basis [l][n] (1 MB)
__device__ __align__(16) uint32_t g_Tpk[NBQ * LQ];        // packed basis [n][l] (1 MB)
__device__ float    g_Fpart[BQ * NBQ * KSPL * WQ];        // DFT partials [b][n][p][c]
__device__ uint32_t g_coefpk[BQ * WQ * NBQ];              // packed coef (1 MB)
__device__ uint32_t g_convpk[4 * WQ * WQ];                // packed conv weights

__device__ __forceinline__ float gelu_exact(float v) {
    return 0.5f * v * (1.0f + erff(v * 0.70710678118654752440f));
}

// bf16 hi/lo packing: low 16 bits = hi part, high 16 bits = lo part
__device__ __forceinline__ uint32_t pk(float v) {
    __nv_bfloat16 h = __float2bfloat16(v);
    __nv_bfloat16 l = __float2bfloat16(v - __bfloat162float(h));
    return (uint32_t)__bfloat16_as_ushort(h) | ((uint32_t)__bfloat16_as_ushort(l) << 16);
}
__device__ __forceinline__ float upk(uint32_t u) {
    return __bfloat162float(__ushort_as_bfloat16((unsigned short)(u & 0xFFFFu)))
         + __bfloat162float(__ushort_as_bfloat16((unsigned short)(u >> 16)));
}

// warp-level bf16 MMA (baseline PTX, sm_80+; tensor pipe)
__device__ __forceinline__ void mma16816(float* d, const uint32_t* a,
                                         uint32_t b0, uint32_t b1) {
    asm volatile(
        "mma.sync.aligned.m16n8k16.row.col.f32.bf16.bf16.f32 "
        "{%0,%1,%2,%3}, {%4,%5,%6,%7}, {%8,%9}, {%0,%1,%2,%3};"
        : "+f"(d[0]), "+f"(d[1]), "+f"(d[2]), "+f"(d[3])
        : "r"(a[0]), "r"(a[1]), "r"(a[2]), "r"(a[3]), "r"(b0), "r"(b1));
}

// ldmatrix x4: loads four 8x8 b16 tiles; tile i's 8 row addresses come from
// lanes 8i..8i+7; output reg i has the canonical mma fragment layout.
__device__ __forceinline__ void ldsm_x4(uint32_t* r, uint32_t addr) {
    asm volatile("ldmatrix.sync.aligned.m8n8.x4.shared.b16 {%0,%1,%2,%3}, [%4];"
                 : "=r"(r[0]), "=r"(r[1]), "=r"(r[2]), "=r"(r[3]) : "r"(addr));
}

// fused kernel smem layout (bytes). Row stride 400B: 16B-aligned (ldmatrix
// requirement) and 100 words = +4 banks/row -> LDSM tiles conflict-free.
#define AS_B 400
#define OFF_A   0                     // A [128 l][AS_B]; post-mainloop: D fp32 [64][129]
#define OFF_BHI 51200                 // B_hi [64 o][AS_B]
#define OFF_BLO 76800                 // B_lo
#define FUSED_SMEM 102400

// ---------------------------------------------------------------------------
// Basis tables.
// ---------------------------------------------------------------------------
__global__ void build_table_kernel() {
    int idx = blockIdx.x * blockDim.x + threadIdx.x;  // 131072
    int k = idx >> 13;
    int l = idx & (LQ - 1);
    int m = (k * l) & (LQ - 1);
    float ang = (float)m * (6.283185307179586476925f / (float)LQ);
    float s, c;
    sincosf(ang, &s, &c);
    g_T[l * NBQ + 2 * k]     = c;
    g_T[l * NBQ + 2 * k + 1] = s;
    g_Tpk[(2 * k) * LQ + l]     = pk(c);
    g_Tpk[(2 * k + 1) * LQ + l] = pk(s);
}

__global__ void convprep_kernel(const float* __restrict__ cw) {
    int idx = blockIdx.x * 256 + threadIdx.x;   // 16384
    g_convpk[idx] = pk(cw[idx]);
}

// ---------------------------------------------------------------------------
// Lifting -> packed h
// ---------------------------------------------------------------------------
__global__ void lift_kernel(const float* __restrict__ x,
                            const float* __restrict__ Pw,
                            const float* __restrict__ Pb,
                            uint32_t* __restrict__ hpk) {
    int idx = blockIdx.x * 256 + threadIdx.x;
    int l = idx & (LQ - 1);
    int w = (idx >> 13) & 63;
    int b = idx >> 19;
    float x0 = x[(b * 2 + 0) * LQ + l];
    float x1 = x[(b * 2 + 1) * LQ + l];
    hpk[idx] = pk(Pw[2 * w] * x0 + Pw[2 * w + 1] * x1 + Pb[w]);
}

// ---------------------------------------------------------------------------
// Scalar forward DFT with half-period folding (validated R5/R7).
// ---------------------------------------------------------------------------
__global__ void __launch_bounds__(128) fwd_dft_kernel(const uint32_t* __restrict__ hpk) {
    __shared__ float Es[64 * 65];
    __shared__ float Os[64 * 65];
    __shared__ __align__(16) float Tt[64 * 32];
    int b = blockIdx.x;
    int ks = blockIdx.y;
    int t = threadIdx.x;
    int cc = t & 31;
    int nq = (t >> 5) << 3;
    float acc0[8] = {0.f,0.f,0.f,0.f,0.f,0.f,0.f,0.f};
    float acc1[8] = {0.f,0.f,0.f,0.f,0.f,0.f,0.f,0.f};
    const int lbase = ks * (LH / KSPL);  // 256

    for (int chk = 0; chk < 4; chk++) {
        int l0 = lbase + chk * 64;
        __syncthreads();
#pragma unroll
        for (int j = 0; j < 32; j++) {
            int idx = t + 128 * j;
            int c = idx >> 6, l = idx & 63;
            const uint32_t* hp = hpk + (size_t)(b * 64 + c) * LQ + l0 + l;
            float v1 = upk(hp[0]);
            float v2 = upk(hp[LH]);
            Es[c * 65 + l] = v1 + v2;
            Os[c * 65 + l] = v1 - v2;
        }
#pragma unroll
        for (int j = 0; j < 4; j++) {
            int idx = t + 128 * j;
            ((float4*)Tt)[idx] = ((const float4*)g_T)[l0 * 8 + idx];
        }
        __syncthreads();
#pragma unroll 4
        for (int l = 0; l < 64; l++) {
            float e0 = Es[cc * 65 + l];
            float e1 = Es[(cc + 32) * 65 + l];
            float o0 = Os[cc * 65 + l];
            float o1 = Os[(cc + 32) * 65 + l];
            float4 bv0 = *(float4*)(Tt + l * 32 + nq);
            float4 bv1 = *(float4*)(Tt + l * 32 + nq + 4);
            acc0[0] += e0 * bv0.x; acc0[1] += e0 * bv0.y;
            acc0[2] += o0 * bv0.z; acc0[3] += o0 * bv0.w;
            acc0[4] += e0 * bv1.x; acc0[5] += e0 * bv1.y;
            acc0[6] += o0 * bv1.z; acc0[7] += o0 * bv1.w;
            acc1[0] += e1 * bv0.x; acc1[1] += e1 * bv0.y;
            acc1[2] += o1 * bv0.z; acc1[3] += o1 * bv0.w;
            acc1[4] += e1 * bv1.x; acc1[5] += e1 * bv1.y;
            acc1[6] += o1 * bv1.z; acc1[7] += o1 * bv1.w;
        }
    }
#pragma unroll
    for (int j = 0; j < 8; j++) {
        int n = nq + j;
        size_t base = ((size_t)(b * NBQ + n) * KSPL + ks) * 64;
        g_Fpart[base + cc]      = acc0[j];
        g_Fpart[base + cc + 32] = acc1[j];
    }
}

// ---------------------------------------------------------------------------
// Mode mixing -> packed coefficients. (validated)
// ---------------------------------------------------------------------------
__global__ void __launch_bounds__(256) mode_mix_kernel(const float* __restrict__ kwr,
                                                       const float* __restrict__ kwi, int ib) {
    int k = blockIdx.x;
    int bg = blockIdx.y;
    int t = threadIdx.x;
    int o = t & 63;
    int bb = t >> 6;
    int b = bg * 4 + bb;
    __shared__ float wrS[64 * 65], wiS[64 * 65];
    __shared__ float HrS[4][64], HsS[4][64];

    const float* wrG = kwr + ((size_t)ib * 16 + k) * 4096;
    const float* wiG = kwi + ((size_t)ib * 16 + k) * 4096;
#pragma unroll
    for (int j = 0; j < 16; j++) {
        int idx = t + 256 * j;
        int row = idx >> 6, col = idx & 63;
        wrS[row * 65 + col] = wrG[idx];
        wiS[row * 65 + col] = wiG[idx];
    }

    float hr = 0.f, hs = 0.f;
    const float* fr = g_Fpart + (size_t)(b * NBQ + 2 * k) * KSPL * 64;
    const float* fs = g_Fpart + (size_t)(b * NBQ + 2 * k + 1) * KSPL * 64;
#pragma unroll
    for (int p = 0; p < KSPL; p++) {
        hr += fr[p * 64 + o];
        hs += fs[p * 64 + o];
    }
    HrS[bb][o] = hr;
    HsS[bb][o] = hs;
    __syncthreads();

    float ar = 0.f, ai = 0.f;
#pragma unroll 8
    for (int i = 0; i < 64; i++) {
        float xr = HrS[bb][i];
        float xi = -HsS[bb][i];
        float wrv = wrS[o * 65 + i];
        float wiv = wiS[o * 65 + i];
        ar += wrv * xr - wiv * xi;
        ai += wrv * xi + wiv * xr;
    }
    const float invL = 1.0f / (float)LQ;
    float cC, cS;
    if (k == 0) { cC = ar * invL;        cS = 0.f; }
    else        { cC = 2.f * ar * invL;  cS = -2.f * ai * invL; }
    g_coefpk[(b * 64 + o) * NBQ + 2 * k]     = pk(cC);
    g_coefpk[(b * 64 + o) * NBQ + 2 * k + 1] = pk(cS);
}

// ---------------------------------------------------------------------------
// Fused block via mma.sync bf16-split with ldmatrix fragment feed.
//   D[128 l, 64 o] = A[l, K=192] x B[o, K=192]^T, passes over B_hi and B_lo.
// Mainloop per kstep: 2 LDSM.x4 (A, one per m16 tile) + 4 LDSM.x4 (B, one
// per (pass, ni-pair)) -> 16 HMMA. Row stride 400B: LDSM conflict-free.
// ---------------------------------------------------------------------------
template <bool LAST>
__global__ void __launch_bounds__(256, 2) fused_mma_kernel(
    const uint32_t* __restrict__ hin, uint32_t* __restrict__ hout,
    const float* __restrict__ cb, int ib,
    const float* __restrict__ Qw, const float* __restrict__ Qb,
    float* __restrict__ outp) {
    extern __shared__ __align__(16) char smem[];
    char* Asm = smem + OFF_A;
    int b = blockIdx.y;
    int t = threadIdx.x;
    int wid = t >> 5;
    int lane = t & 31;
    int l0 = blockIdx.x * 128;

    // ---- stage A: 128 l x 96 ch (packed u32 = k-slot pairs) -------------
    const uint32_t* hsrc = hin + (size_t)b * 64 * LQ;
#pragma unroll
    for (int j = 0; j < 48; j++) {
        int id = t + 256 * j;            // 12288 = 96 ch x 128 l
        int c = id >> 7;
        int l = id & 127;
        const uint32_t* src = (c < 32) ? (g_Tpk + (size_t)c * LQ)
                                       : (hsrc + (size_t)(c - 32) * LQ);
        *(uint32_t*)(Asm + l * AS_B + c * 4) = src[l0 + l];
    }
    // ---- stage B: 64 o x 96 c -> (wh,wh) / (wl,wl) ----------------------
#pragma unroll
    for (int j = 0; j < 24; j++) {
        int id = t + 256 * j;            // 6144 = 64 o x 96 c
        int o = id / 96;
        int c = id - o * 96;
        uint32_t u = (c < 32) ? g_coefpk[((size_t)b * 64 + o) * NBQ + c]
                              : g_convpk[ib * 4096 + o * 64 + (c - 32)];
        uint32_t wh = u & 0xFFFFu;
        uint32_t wl = u >> 16;
        *(uint32_t*)(smem + OFF_BHI + o * AS_B + c * 4) = wh | (wh << 16);
        *(uint32_t*)(smem + OFF_BLO + o * AS_B + c * 4) = wl | (wl << 16);
    }
    __syncthreads();

    // ---- ldmatrix lane addressing ---------------------------------------
    int wm = wid >> 1;                   // m-rows [wm*32, +32)
    int wn = wid & 1;                    // o-cols [wn*32, +32)
    int r = lane >> 2;
    int q = lane & 3;
    int g = lane >> 3;                   // ldmatrix group 0..3
    int rr = lane & 7;
    uint32_t sbase = (uint32_t)__cvta_generic_to_shared(smem);
    // A tiles (a0,a1,a2,a3) = (m0-7@k, m8-15@k, m0-7@k+8, m8-15@k+8)
    uint32_t aAddr0 = sbase + OFF_A
                    + (uint32_t)((wm * 32 + ((g & 1) ? 8 : 0) + rr) * AS_B)
                    + ((g & 2) ? 16u : 0u);
    uint32_t aAddr1 = aAddr0 + 16 * AS_B;
    // B tiles (b0_n, b1_n, b0_n', b1_n') = (o0-7@k, o0-7@k+8, o8-15@k, o8-15@k+8)
    uint32_t bOff = (uint32_t)((wn * 32 + ((g & 2) ? 8 : 0) + rr) * AS_B)
                  + ((g & 1) ? 16u : 0u);
    uint32_t bAddrH0 = sbase + OFF_BHI + bOff;
    uint32_t bAddrH1 = bAddrH0 + 16 * AS_B;
    uint32_t bAddrL0 = sbase + OFF_BLO + bOff;
    uint32_t bAddrL1 = bAddrL0 + 16 * AS_B;

    float d[2][4][4];
#pragma unroll
    for (int mi = 0; mi < 2; mi++)
#pragma unroll
        for (int ni = 0; ni < 4; ni++)
#pragma unroll
            for (int e = 0; e < 4; e++) d[mi][ni][e] = 0.f;

#pragma unroll
    for (int ks = 0; ks < 12; ks++) {
        uint32_t kb = ks * 32;           // 16 k-slots = 32 bytes
        uint32_t a0[4], a1[4], B0[4], B1[4];
        ldsm_x4(a0, aAddr0 + kb);
        ldsm_x4(a1, aAddr1 + kb);
        // pass hi
        ldsm_x4(B0, bAddrH0 + kb);
        ldsm_x4(B1, bAddrH1 + kb);
        mma16816(d[0][0], a0, B0[0], B0[1]);
        mma16816(d[0][1], a0, B0[2], B0[3]);
        mma16816(d[0][2], a0, B1[0], B1[1]);
        mma16816(d[0][3], a0, B1[2], B1[3]);
        mma16816(d[1][0], a1, B0[0], B0[1]);
        mma16816(d[1][1], a1, B0[2], B0[3]);
        mma16816(d[1][2], a1, B1[0], B1[1]);
        mma16816(d[1][3], a1, B1[2], B1[3]);
        // pass lo
        ldsm_x4(B0, bAddrL0 + kb);
        ldsm_x4(B1, bAddrL1 + kb);
        mma16816(d[0][0], a0, B0[0], B0[1]);
        mma16816(d[0][1], a0, B0[2], B0[3]);
        mma16816(d[0][2], a0, B1[0], B1[1]);
        mma16816(d[0][3], a0, B1[2], B1[3]);
        mma16816(d[1][0], a1, B0[0], B0[1]);
        mma16816(d[1][1], a1, B0[2], B0[3]);
        mma16816(d[1][2], a1, B1[0], B1[1]);
        mma16816(d[1][3], a1, B1[2], B1[3]);
    }

    // ---- stage D fragments to smem (reuse A region) ---------------------
    __syncthreads();
    float* D = (float*)Asm;              // D[o][129]
#pragma unroll
    for (int mi = 0; mi < 2; mi++)
#pragma unroll
        for (int ni = 0; ni < 4; ni++) {
            int l = wm * 32 + mi * 16 + r;
            int o = wn * 32 + ni * 8 + q * 2;
            D[o * 129 + l]           = d[mi][ni][0];
            D[(o + 1) * 129 + l]     = d[mi][ni][1];
            D[o * 129 + l + 8]       = d[mi][ni][2];
            D[(o + 1) * 129 + l + 8] = d[mi][ni][3];
        }
    __syncthreads();

    if (!LAST) {
#pragma unroll
        for (int j = 0; j < 32; j++) {
            int idx = t + 256 * j;
            int o = idx >> 7;
            int l = idx & 127;
            float v = D[o * 129 + l] + __ldg(&cb[ib * 64 + o]);
            hout[((size_t)b * 64 + o) * LQ + l0 + l] = pk(gelu_exact(v));
        }
    } else {
        float* partS = (float*)(smem + OFF_BHI);
        int l = t & 127;
        int ob = t >> 7;
        float s = 0.f;
#pragma unroll
        for (int j = 0; j < 32; j++) {
            int o = ob + 2 * j;
            float v = D[o * 129 + l] + __ldg(&cb[ib * 64 + o]);
            s += __ldg(&Qw[o]) * gelu_exact(v);
        }
        partS[ob * 128 + l] = s;
        __syncthreads();
        if (t < 128)
            outp[(size_t)b * LQ + l0 + t] = partS[t] + partS[128 + t] + __ldg(&Qb[0]);
    }
}

// ---------------------------------------------------------------------------
extern "C" void kernel_launch(void* const* d_in, const int* in_sizes, int n_in,
                              void* d_out, int out_size) {
    const float* x   = (const float*)d_in[0];
    const float* Pw  = (const float*)d_in[1];
    const float* Pb  = (const float*)d_in[2];
    const float* kwr = (const float*)d_in[3];
    const float* kwi = (const float*)d_in[4];
    const float* cw  = (const float*)d_in[5];
    const float* cb  = (const float*)d_in[6];
    const float* Qw  = (const float*)d_in[7];
    const float* Qb  = (const float*)d_in[8];
    float* out = (float*)d_out;

    uint32_t *hA = nullptr, *hB = nullptr;
    cudaGetSymbolAddress((void**)&hA, g_hpkA);
    cudaGetSymbolAddress((void**)&hB, g_hpkB);

    cudaFuncSetAttribute(fused_mma_kernel<false>,
                         cudaFuncAttributeMaxDynamicSharedMemorySize, FUSED_SMEM);
    cudaFuncSetAttribute(fused_mma_kernel<true>,
                         cudaFuncAttributeMaxDynamicSharedMemorySize, FUSED_SMEM);

    build_table_kernel<<<(LQ * MQ) / 256, 256>>>();
    convprep_kernel<<<64, 256>>>(cw);
    lift_kernel<<<(BQ * WQ * LQ) / 256, 256>>>(x, Pw, Pb, hA);

    uint32_t* cur = hA;
    uint32_t* nxt = hB;
    for (int ib = 0; ib < 4; ib++) {
        fwd_dft_kernel<<<dim3(BQ, KSPL), 128>>>(cur);
        mode_mix_kernel<<<dim3(16, 8), 256>>>(kwr, kwi, ib);
        if (ib < 3) {
            fused_mma_kernel<false><<<dim3(LQ / 128, BQ), 256, FUSED_SMEM>>>(
                cur, nxt, cb, ib, Qw, Qb, out);
        } else {
            fused_mma_kernel<true><<<dim3(LQ / 128, BQ), 256, FUSED_SMEM>>>(
                cur, nxt, cb, ib, Qw, Qb, out);
        }
        uint32_t* tmp = cur; cur = nxt; nxt = tmp;
    }
}

// round 13
// speedup vs baseline: 1.3984x; 1.1095x over previous
#include <cuda_runtime.h>
#include <cuda_bf16.h>
#include <math.h>
#include <stdint.h>

// Problem constants
#define BQ 32
#define WQ 64
#define MQ 16
#define LQ 8192
#define NBQ 32
#define KSPL 16

// ---------------- scratch (device globals: allocation-free rule) ----------
__device__ __align__(16) uint32_t g_hpkA[BQ * WQ * LQ];   // packed bf16 hi|lo h (64 MB)
__device__ __align__(16) uint32_t g_hpkB[BQ * WQ * LQ];   // 64 MB
__device__ __align__(16) uint32_t g_Tpk[NBQ * LQ];        // packed basis [n][l] (1 MB)
__device__ __align__(16) uint32_t g_Bhi[NBQ * LQ];        // (T_hi,T_hi) pairs [n][l]
__device__ __align__(16) uint32_t g_Blo[NBQ * LQ];        // (T_lo,T_lo) pairs [n][l]
__device__ float    g_Fpart[BQ * NBQ * KSPL * WQ];        // DFT partials [b][n][p][c]
__device__ uint32_t g_coefpk[BQ * WQ * NBQ];              // packed coef (1 MB)
__device__ uint32_t g_convpk[4 * WQ * WQ];                // packed conv weights

__device__ __forceinline__ float gelu_exact(float v) {
    return 0.5f * v * (1.0f + erff(v * 0.70710678118654752440f));
}

// bf16 hi/lo packing: low 16 bits = hi part, high 16 bits = lo part
__device__ __forceinline__ uint32_t pk(float v) {
    __nv_bfloat16 h = __float2bfloat16(v);
    __nv_bfloat16 l = __float2bfloat16(v - __bfloat162float(h));
    return (uint32_t)__bfloat16_as_ushort(h) | ((uint32_t)__bfloat16_as_ushort(l) << 16);
}

// warp-level bf16 MMA (baseline PTX, sm_80+; tensor pipe)
__device__ __forceinline__ void mma16816(float* d, const uint32_t* a,
                                         uint32_t b0, uint32_t b1) {
    asm volatile(
        "mma.sync.aligned.m16n8k16.row.col.f32.bf16.bf16.f32 "
        "{%0,%1,%2,%3}, {%4,%5,%6,%7}, {%8,%9}, {%0,%1,%2,%3};"
        : "+f"(d[0]), "+f"(d[1]), "+f"(d[2]), "+f"(d[3])
        : "r"(a[0]), "r"(a[1]), "r"(a[2]), "r"(a[3]), "r"(b0), "r"(b1));
}

__device__ __forceinline__ void ldsm_x4(uint32_t* r, uint32_t addr) {
    asm volatile("ldmatrix.sync.aligned.m8n8.x4.shared.b16 {%0,%1,%2,%3}, [%4];"
                 : "=r"(r[0]), "=r"(r[1]), "=r"(r[2]), "=r"(r[3]) : "r"(addr));
}

// cp.async 16B (baseline PTX, sm_80+)
__device__ __forceinline__ void cp_async16(uint32_t saddr, const void* gptr) {
    asm volatile("cp.async.cg.shared.global [%0], [%1], 16;"
                 :: "r"(saddr), "l"(__cvta_generic_to_global(gptr)) : "memory");
}
#define CP_COMMIT() asm volatile("cp.async.commit_group;" ::: "memory")
#define CP_WAIT1()  asm volatile("cp.async.wait_group 1;" ::: "memory")

// fused kernel smem layout (bytes). Row stride 400B: 16B-aligned and
// +4 banks/row -> LDSM conflict-free.
#define AS_B 400
#define OFF_A   0
#define OFF_BHI 51200
#define OFF_BLO 76800
#define FUSED_SMEM 102400

// fwd kernel smem: 2 stages of {A[64][68w], Bh[32][68w], Bl[32][68w]};
// stride 68 words = 272B (16B-aligned, +4 banks/row -> LDSM conflict-free).
// Dw reduction overlays both stages after the mainloop.
#define FA_W 68
#define FSTAGE (128 * FA_W)           // words per stage (A:64 + Bh:32 + Bl:32 rows)
#define FWD_SMEM (2 * FSTAGE * 4)     // 69632 B

// ---------------------------------------------------------------------------
// Basis tables.
// ---------------------------------------------------------------------------
__global__ void build_table_kernel() {
    int idx = blockIdx.x * blockDim.x + threadIdx.x;  // 131072
    int k = idx >> 13;
    int l = idx & (LQ - 1);
    int m = (k * l) & (LQ - 1);
    float ang = (float)m * (6.283185307179586476925f / (float)LQ);
    float s, c;
    sincosf(ang, &s, &c);
    uint32_t cp = pk(c), sp = pk(s);
    g_Tpk[(2 * k) * LQ + l]     = cp;
    g_Tpk[(2 * k + 1) * LQ + l] = sp;
    uint32_t ch = cp & 0xFFFFu, cl = cp >> 16;
    uint32_t sh = sp & 0xFFFFu, sl = sp >> 16;
    g_Bhi[(2 * k) * LQ + l]     = ch | (ch << 16);
    g_Blo[(2 * k) * LQ + l]     = cl | (cl << 16);
    g_Bhi[(2 * k + 1) * LQ + l] = sh | (sh << 16);
    g_Blo[(2 * k + 1) * LQ + l] = sl | (sl << 16);
}

__global__ void convprep_kernel(const float* __restrict__ cw) {
    int idx = blockIdx.x * 256 + threadIdx.x;   // 16384
    g_convpk[idx] = pk(cw[idx]);
}

// ---------------------------------------------------------------------------
// Lifting -> packed h
// ---------------------------------------------------------------------------
__global__ void lift_kernel(const float* __restrict__ x,
                            const float* __restrict__ Pw,
                            const float* __restrict__ Pb,
                            uint32_t* __restrict__ hpk) {
    int idx = blockIdx.x * 256 + threadIdx.x;
    int l = idx & (LQ - 1);
    int w = (idx >> 13) & 63;
    int b = idx >> 19;
    float x0 = x[(b * 2 + 0) * LQ + l];
    float x1 = x[(b * 2 + 1) * LQ + l];
    hpk[idx] = pk(Pw[2 * w] * x0 + Pw[2 * w + 1] * x1 + Pb[w]);
}

// ---------------------------------------------------------------------------
// Forward DFT via mma.sync bf16-split, cp.async double-buffered + ldmatrix:
//   Fpart[b,ks][c=64, n=32] = sum over 512-word slice of h[c,l] * T[l,n]
// A k-slots (2l,2l+1) = packed h word (hi,lo) -- zero repack (R8-validated).
// 8 chunks x 64 words; warp w owns kstep w (16 slots): 8 ldsm_x4 -> 32 HMMA.
// Epilogue: conflict-free Dw cross-warp reduce (R8-validated), coalesced store.
// ---------------------------------------------------------------------------
__global__ void __launch_bounds__(256, 2) fwd_mma_kernel(const uint32_t* __restrict__ hpk) {
    extern __shared__ __align__(16) uint32_t sw[];
    int b = blockIdx.x;
    int ks = blockIdx.y;
    int t = threadIdx.x;
    int w = t >> 5;
    int lane = t & 31;
    int r = lane >> 2;
    int q = lane & 3;
    int g = lane >> 3;
    int rr = lane & 7;

    const uint32_t* hb = hpk + (size_t)b * 64 * LQ;
    const int base = ks * 512;
    uint32_t sbase = (uint32_t)__cvta_generic_to_shared(sw);

    // ldmatrix base addresses (stage 0); stage 1 adds FSTAGE*4 bytes.
    // A tiles (m0-7@k, m8-15@k, m0-7@k+16B, m8-15@k+16B) per m16 block mi.
    uint32_t aBase = sbase + (uint32_t)((((g & 1) ? 8 : 0) + rr) * (FA_W * 4))
                   + ((g & 2) ? 16u : 0u) + (uint32_t)(w * 32);
    // B tiles (n0-7@k, n0-7@k+8, n8-15@k, n8-15@k+8) per pass.
    uint32_t bBase = sbase + (uint32_t)((64 + ((g & 2) ? 8 : 0) + rr) * (FA_W * 4))
                   + ((g & 1) ? 16u : 0u) + (uint32_t)(w * 32);

    float d[4][4][4];
#pragma unroll
    for (int mi = 0; mi < 4; mi++)
#pragma unroll
        for (int ni = 0; ni < 4; ni++)
#pragma unroll
            for (int e = 0; e < 4; e++) d[mi][ni][e] = 0.f;

    // ---- staging issue: chunk chk into stage st ------------------------
    auto issue = [&](int chk, int st) {
        uint32_t sA = sbase + (uint32_t)(st * FSTAGE * 4);
        int lb = base + chk * 64;
#pragma unroll
        for (int j = 0; j < 4; j++) {          // A: 1024 x 16B
            int id = t + 256 * j;
            int c = id >> 4, col = (id & 15) * 4;
            cp_async16(sA + (uint32_t)((c * FA_W + col) * 4),
                       hb + (size_t)c * LQ + lb + col);
        }
#pragma unroll
        for (int j = 0; j < 4; j++) {          // B: 1024 x 16B (hi then lo)
            int id = t + 256 * j;
            int half = id >> 9;
            int n = (id >> 4) & 31, col = (id & 15) * 4;
            const uint32_t* gt = (half ? g_Blo : g_Bhi) + (size_t)n * LQ + lb + col;
            cp_async16(sA + (uint32_t)(((64 + half * 32 + n) * FA_W + col) * 4), gt);
        }
    };

    issue(0, 0); CP_COMMIT();
    issue(1, 1); CP_COMMIT();

    for (int chk = 0; chk < 8; chk++) {
        CP_WAIT1();                    // groups 0..chk complete
        __syncthreads();
        uint32_t soff = (uint32_t)((chk & 1) * FSTAGE * 4);
        uint32_t a[4][4];
#pragma unroll
        for (int mi = 0; mi < 4; mi++)
            ldsm_x4(a[mi], aBase + soff + (uint32_t)(mi * 16 * FA_W * 4));
#pragma unroll
        for (int pass = 0; pass < 2; pass++) {
            uint32_t B0[4], B1[4];
            uint32_t bp = bBase + soff + (uint32_t)(pass * 32 * FA_W * 4);
            ldsm_x4(B0, bp);
            ldsm_x4(B1, bp + 16 * FA_W * 4);
#pragma unroll
            for (int mi = 0; mi < 4; mi++) {
                mma16816(d[mi][0], a[mi], B0[0], B0[1]);
                mma16816(d[mi][1], a[mi], B0[2], B0[3]);
                mma16816(d[mi][2], a[mi], B1[0], B1[1]);
                mma16816(d[mi][3], a[mi], B1[2], B1[3]);
            }
        }
        __syncthreads();               // stage free before refill
        if (chk + 2 < 8) issue(chk + 2, chk & 1);
        CP_COMMIT();                   // empty group keeps wait(1) exact
    }

    // ---- Dw reduce (overlay; banks 8q+r -> conflict-free) ---------------
    float* Dw = (float*)sw;            // [8][32 n][FA_W]
    float* dw = Dw + w * (32 * FA_W);
#pragma unroll
    for (int mi = 0; mi < 4; mi++)
#pragma unroll
        for (int ni = 0; ni < 4; ni++) {
            int c = mi * 16 + r;
            int n = ni * 8 + 2 * q;
            dw[n * FA_W + c]           = d[mi][ni][0];
            dw[(n + 1) * FA_W + c]     = d[mi][ni][1];
            dw[n * FA_W + c + 8]       = d[mi][ni][2];
            dw[(n + 1) * FA_W + c + 8] = d[mi][ni][3];
        }
    __syncthreads();

#pragma unroll
    for (int j = 0; j < 8; j++) {
        int idx = t + 256 * j;          // 2048 = 32 n x 64 c
        int n = idx >> 6;
        int c = idx & 63;
        float s = 0.f;
#pragma unroll
        for (int ww = 0; ww < 8; ww++)
            s += Dw[ww * (32 * FA_W) + n * FA_W + c];
        g_Fpart[((size_t)(b * NBQ + n) * KSPL + ks) * 64 + c] = s;
    }
}

// ---------------------------------------------------------------------------
// Mode mixing -> packed coefficients. (validated)
// ---------------------------------------------------------------------------
__global__ void __launch_bounds__(256) mode_mix_kernel(const float* __restrict__ kwr,
                                                       const float* __restrict__ kwi, int ib) {
    int k = blockIdx.x;
    int bg = blockIdx.y;
    int t = threadIdx.x;
    int o = t & 63;
    int bb = t >> 6;
    int b = bg * 4 + bb;
    __shared__ float wrS[64 * 65], wiS[64 * 65];
    __shared__ float HrS[4][64], HsS[4][64];

    const float* wrG = kwr + ((size_t)ib * 16 + k) * 4096;
    const float* wiG = kwi + ((size_t)ib * 16 + k) * 4096;
#pragma unroll
    for (int j = 0; j < 16; j++) {
        int idx = t + 256 * j;
        int row = idx >> 6, col = idx & 63;
        wrS[row * 65 + col] = wrG[idx];
        wiS[row * 65 + col] = wiG[idx];
    }

    float hr = 0.f, hs = 0.f;
    const float* fr = g_Fpart + (size_t)(b * NBQ + 2 * k) * KSPL * 64;
    const float* fs = g_Fpart + (size_t)(b * NBQ + 2 * k + 1) * KSPL * 64;
#pragma unroll
    for (int p = 0; p < KSPL; p++) {
        hr += fr[p * 64 + o];
        hs += fs[p * 64 + o];
    }
    HrS[bb][o] = hr;
    HsS[bb][o] = hs;
    __syncthreads();

    float ar = 0.f, ai = 0.f;
#pragma unroll 8
    for (int i = 0; i < 64; i++) {
        float xr = HrS[bb][i];
        float xi = -HsS[bb][i];
        float wrv = wrS[o * 65 + i];
        float wiv = wiS[o * 65 + i];
        ar += wrv * xr - wiv * xi;
        ai += wrv * xi + wiv * xr;
    }
    const float invL = 1.0f / (float)LQ;
    float cC, cS;
    if (k == 0) { cC = ar * invL;        cS = 0.f; }
    else        { cC = 2.f * ar * invL;  cS = -2.f * ai * invL; }
    g_coefpk[(b * 64 + o) * NBQ + 2 * k]     = pk(cC);
    g_coefpk[(b * 64 + o) * NBQ + 2 * k + 1] = pk(cS);
}

// ---------------------------------------------------------------------------
// Fused block via mma.sync bf16-split with ldmatrix feed. (R12 — validated)
// ---------------------------------------------------------------------------
template <bool LAST>
__global__ void __launch_bounds__(256, 2) fused_mma_kernel(
    const uint32_t* __restrict__ hin, uint32_t* __restrict__ hout,
    const float* __restrict__ cb, int ib,
    const float* __restrict__ Qw, const float* __restrict__ Qb,
    float* __restrict__ outp) {
    extern __shared__ __align__(16) char smem[];
    char* Asm = smem + OFF_A;
    int b = blockIdx.y;
    int t = threadIdx.x;
    int wid = t >> 5;
    int lane = t & 31;
    int l0 = blockIdx.x * 128;

    const uint32_t* hsrc = hin + (size_t)b * 64 * LQ;
#pragma unroll
    for (int j = 0; j < 48; j++) {
        int id = t + 256 * j;            // 12288 = 96 ch x 128 l
        int c = id >> 7;
        int l = id & 127;
        const uint32_t* src = (c < 32) ? (g_Tpk + (size_t)c * LQ)
                                       : (hsrc + (size_t)(c - 32) * LQ);
        *(uint32_t*)(Asm + l * AS_B + c * 4) = src[l0 + l];
    }
#pragma unroll
    for (int j = 0; j < 24; j++) {
        int id = t + 256 * j;            // 6144 = 64 o x 96 c
        int o = id / 96;
        int c = id - o * 96;
        uint32_t u = (c < 32) ? g_coefpk[((size_t)b * 64 + o) * NBQ + c]
                              : g_convpk[ib * 4096 + o * 64 + (c - 32)];
        uint32_t wh = u & 0xFFFFu;
        uint32_t wl = u >> 16;
        *(uint32_t*)(smem + OFF_BHI + o * AS_B + c * 4) = wh | (wh << 16);
        *(uint32_t*)(smem + OFF_BLO + o * AS_B + c * 4) = wl | (wl << 16);
    }
    __syncthreads();

    int wm = wid >> 1;
    int wn = wid & 1;
    int r = lane >> 2;
    int q = lane & 3;
    int g = lane >> 3;
    int rr = lane & 7;
    uint32_t sbase = (uint32_t)__cvta_generic_to_shared(smem);
    uint32_t aAddr0 = sbase + OFF_A
                    + (uint32_t)((wm * 32 + ((g & 1) ? 8 : 0) + rr) * AS_B)
                    + ((g & 2) ? 16u : 0u);
    uint32_t aAddr1 = aAddr0 + 16 * AS_B;
    uint32_t bOff = (uint32_t)((wn * 32 + ((g & 2) ? 8 : 0) + rr) * AS_B)
                  + ((g & 1) ? 16u : 0u);
    uint32_t bAddrH0 = sbase + OFF_BHI + bOff;
    uint32_t bAddrH1 = bAddrH0 + 16 * AS_B;
    uint32_t bAddrL0 = sbase + OFF_BLO + bOff;
    uint32_t bAddrL1 = bAddrL0 + 16 * AS_B;

    float d[2][4][4];
#pragma unroll
    for (int mi = 0; mi < 2; mi++)
#pragma unroll
        for (int ni = 0; ni < 4; ni++)
#pragma unroll
            for (int e = 0; e < 4; e++) d[mi][ni][e] = 0.f;

#pragma unroll
    for (int ks = 0; ks < 12; ks++) {
        uint32_t kb = ks * 32;
        uint32_t a0[4], a1[4], B0[4], B1[4];
        ldsm_x4(a0, aAddr0 + kb);
        ldsm_x4(a1, aAddr1 + kb);
        ldsm_x4(B0, bAddrH0 + kb);
        ldsm_x4(B1, bAddrH1 + kb);
        mma16816(d[0][0], a0, B0[0], B0[1]);
        mma16816(d[0][1], a0, B0[2], B0[3]);
        mma16816(d[0][2], a0, B1[0], B1[1]);
        mma16816(d[0][3], a0, B1[2], B1[3]);
        mma16816(d[1][0], a1, B0[0], B0[1]);
        mma16816(d[1][1], a1, B0[2], B0[3]);
        mma16816(d[1][2], a1, B1[0], B1[1]);
        mma16816(d[1][3], a1, B1[2], B1[3]);
        ldsm_x4(B0, bAddrL0 + kb);
        ldsm_x4(B1, bAddrL1 + kb);
        mma16816(d[0][0], a0, B0[0], B0[1]);
        mma16816(d[0][1], a0, B0[2], B0[3]);
        mma16816(d[0][2], a0, B1[0], B1[1]);
        mma16816(d[0][3], a0, B1[2], B1[3]);
        mma16816(d[1][0], a1, B0[0], B0[1]);
        mma16816(d[1][1], a1, B0[2], B0[3]);
        mma16816(d[1][2], a1, B1[0], B1[1]);
        mma16816(d[1][3], a1, B1[2], B1[3]);
    }

    __syncthreads();
    float* D = (float*)Asm;              // D[o][129]
#pragma unroll
    for (int mi = 0; mi < 2; mi++)
#pragma unroll
        for (int ni = 0; ni < 4; ni++) {
            int l = wm * 32 + mi * 16 + r;
            int o = wn * 32 + ni * 8 + q * 2;
            D[o * 129 + l]           = d[mi][ni][0];
            D[(o + 1) * 129 + l]     = d[mi][ni][1];
            D[o * 129 + l + 8]       = d[mi][ni][2];
            D[(o + 1) * 129 + l + 8] = d[mi][ni][3];
        }
    __syncthreads();

    if (!LAST) {
#pragma unroll
        for (int j = 0; j < 32; j++) {
            int idx = t + 256 * j;
            int o = idx >> 7;
            int l = idx & 127;
            float v = D[o * 129 + l] + __ldg(&cb[ib * 64 + o]);
            hout[((size_t)b * 64 + o) * LQ + l0 + l] = pk(gelu_exact(v));
        }
    } else {
        float* partS = (float*)(smem + OFF_BHI);
        int l = t & 127;
        int ob = t >> 7;
        float s = 0.f;
#pragma unroll
        for (int j = 0; j < 32; j++) {
            int o = ob + 2 * j;
            float v = D[o * 129 + l] + __ldg(&cb[ib * 64 + o]);
            s += __ldg(&Qw[o]) * gelu_exact(v);
        }
        partS[ob * 128 + l] = s;
        __syncthreads();
        if (t < 128)
            outp[(size_t)b * LQ + l0 + t] = partS[t] + partS[128 + t] + __ldg(&Qb[0]);
    }
}

// ---------------------------------------------------------------------------
extern "C" void kernel_launch(void* const* d_in, const int* in_sizes, int n_in,
                              void* d_out, int out_size) {
    const float* x   = (const float*)d_in[0];
    const float* Pw  = (const float*)d_in[1];
    const float* Pb  = (const float*)d_in[2];
    const float* kwr = (const float*)d_in[3];
    const float* kwi = (const float*)d_in[4];
    const float* cw  = (const float*)d_in[5];
    const float* cb  = (const float*)d_in[6];
    const float* Qw  = (const float*)d_in[7];
    const float* Qb  = (const float*)d_in[8];
    float* out = (float*)d_out;

    uint32_t *hA = nullptr, *hB = nullptr;
    cudaGetSymbolAddress((void**)&hA, g_hpkA);
    cudaGetSymbolAddress((void**)&hB, g_hpkB);

    cudaFuncSetAttribute(fused_mma_kernel<false>,
                         cudaFuncAttributeMaxDynamicSharedMemorySize, FUSED_SMEM);
    cudaFuncSetAttribute(fused_mma_kernel<true>,
                         cudaFuncAttributeMaxDynamicSharedMemorySize, FUSED_SMEM);
    cudaFuncSetAttribute(fwd_mma_kernel,
                         cudaFuncAttributeMaxDynamicSharedMemorySize, FWD_SMEM);

    build_table_kernel<<<(LQ * MQ) / 256, 256>>>();
    convprep_kernel<<<64, 256>>>(cw);
    lift_kernel<<<(BQ * WQ * LQ) / 256, 256>>>(x, Pw, Pb, hA);

    uint32_t* cur = hA;
    uint32_t* nxt = hB;
    for (int ib = 0; ib < 4; ib++) {
        fwd_mma_kernel<<<dim3(BQ, KSPL), 256, FWD_SMEM>>>(cur);
        mode_mix_kernel<<<dim3(16, 8), 256>>>(kwr, kwi, ib);
        if (ib < 3) {
            fused_mma_kernel<false><<<dim3(LQ / 128, BQ), 256, FUSED_SMEM>>>(
                cur, nxt, cb, ib, Qw, Qb, out);
        } else {
            fused_mma_kernel<true><<<dim3(LQ / 128, BQ), 256, FUSED_SMEM>>>(
                cur, nxt, cb, ib, Qw, Qb, out);
        }
        uint32_t* tmp = cur; cur = nxt; nxt = tmp;
    }
}